// round 16
// baseline (speedup 1.0000x reference)
#include <cuda_runtime.h>
#include <math.h>

#define H 1024
#define L 128
#define V 50257

// ---- scratch (device globals; no allocation allowed) ----
__device__ __align__(16) float g_attn_logits[L];
__device__ __align__(16) float g_with_attn[H];
__device__ __align__(16) float g_rnn_in[H];
__device__ __align__(16) float g_gh[3 * H];      // W_hh @ h0 + b_hh (computed in K2's extra blocks)
__device__ __align__(16) float g_hnew[H];
__device__ __align__(16) float g_logits[V + 3];
__device__ float g_sumexp;

__device__ __forceinline__ float warp_sum(float v) {
#pragma unroll
    for (int o = 16; o > 0; o >>= 1) v += __shfl_xor_sync(0xffffffffu, v, o);
    return v;
}

__device__ __forceinline__ float dot4(float4 a, float4 b) {
    return a.x * b.x + a.y * b.y + a.z * b.z + a.w * b.w;
}

// ---- K1: attention logits (blocks 0..127) + init (block 128) ----
__global__ void __launch_bounds__(256) k_attn_logits(const int* __restrict__ x,
                              const float* __restrict__ hidden,
                              const float* __restrict__ emb,
                              const float* __restrict__ attn_W,
                              const float* __restrict__ attn_b) {
    int l = blockIdx.x;
    int t = threadIdx.x;         // 0..255
    if (l == 128) {              // init block: zero with_attn, reset scalars
        *(float4*)(g_with_attn + t * 4) = make_float4(0.f, 0.f, 0.f, 0.f);
        if (t == 0) g_sumexp = 0.f;
        return;
    }
    const float* erow = emb + (long long)x[0] * H;
    const float* wrow = attn_W + (long long)l * 2 * H;
    int j = t * 4;
    float4 w0 = *(const float4*)(wrow + j);
    float4 c0 = *(const float4*)(erow + j);
    float4 w1 = *(const float4*)(wrow + H + j);
    float4 c1 = *(const float4*)(hidden + j);
    float acc = dot4(w0, c0) + dot4(w1, c1);
    acc = warp_sum(acc);
    __shared__ float s[8];
    if ((t & 31) == 0) s[t >> 5] = acc;
    __syncthreads();
    if (t < 8) {
        float v = s[t];
#pragma unroll
        for (int o = 4; o > 0; o >>= 1) v += __shfl_xor_sync(0xffu, v, o);
        if (t == 0) g_attn_logits[l] = v + attn_b[l];
    }
}

// ---- K2: blocks 0..15 = softmax + with_attn (sync on K1);
//          blocks 16..399 = gh rows (input-only, NO sync — overlaps K1) ----
__global__ void __launch_bounds__(256) k_with_attn(const float* __restrict__ enc,
                                                   const float* __restrict__ hidden,
                                                   const float* __restrict__ W_hh,
                                                   const float* __restrict__ b_hh,
                                                   float* __restrict__ out_attn) {
    int b = blockIdx.x;
    int t = threadIdx.x;
    int w = t >> 5;
    int lane = t & 31;
    if (b >= 16) {
        // gh[r] = dot(W_hh[r], h0) + b_hh[r], warp per row; inputs only
        int r = (b - 16) * 8 + w;        // 0..3071
        const float* wrow = W_hh + (long long)r * H;
        float4 a[8];
#pragma unroll
        for (int k = 0; k < 8; k++) a[k] = *(const float4*)(wrow + k * 128 + lane * 4);
        float acc = 0.f;
#pragma unroll
        for (int k = 0; k < 8; k++) acc += dot4(a[k], *(const float4*)(hidden + k * 128 + lane * 4));
        acc = warp_sum(acc);
        if (lane == 0) g_gh[r] = acc + b_hh[r];
        return;
    }
    __shared__ float sw[L];
    __shared__ float redm[4], reds[4];
    int cc = b & 3;                      // col chunk
    int rc = b >> 2;                     // row chunk
    int col = cc * 256 + t;
    int l0 = rc * 32;
    // prefetch this block's enc chunk (independent of K1) into registers
    float e0[8], e1[8], e2[8], e3[8];
#pragma unroll
    for (int j = 0; j < 8; j++) e0[j] = __ldg(enc + (l0 + j * 4) * H + col);
#pragma unroll
    for (int j = 0; j < 8; j++) e1[j] = __ldg(enc + (l0 + j * 4 + 1) * H + col);
#pragma unroll
    for (int j = 0; j < 8; j++) e2[j] = __ldg(enc + (l0 + j * 4 + 2) * H + col);
#pragma unroll
    for (int j = 0; j < 8; j++) e3[j] = __ldg(enc + (l0 + j * 4 + 3) * H + col);

    cudaGridDependencySynchronize();    // wait for K1 (attn logits + init)

    float v = 0.f;
    if (t < L) {
        v = g_attn_logits[t];
        float m = v;
#pragma unroll
        for (int o = 16; o > 0; o >>= 1) m = fmaxf(m, __shfl_xor_sync(0xffffffffu, m, o));
        if (lane == 0) redm[t >> 5] = m;
    }
    __syncthreads();
    float m4 = fmaxf(fmaxf(redm[0], redm[1]), fmaxf(redm[2], redm[3]));
    if (t < L) {
        float e = expf(v - m4);
        float ss = warp_sum(e);
        if (lane == 0) reds[t >> 5] = ss;
        sw[t] = e;
    }
    __syncthreads();
    float tot = (reds[0] + reds[1]) + (reds[2] + reds[3]);
    if (t < L) {
        sw[t] = sw[t] / tot;
        if (b == 0) out_attn[t] = sw[t];
    }
    __syncthreads();
    float acc0 = 0.f, acc1 = 0.f, acc2 = 0.f, acc3 = 0.f;
#pragma unroll
    for (int j = 0; j < 8; j++) {
        acc0 += sw[l0 + j * 4 + 0] * e0[j];
        acc1 += sw[l0 + j * 4 + 1] * e1[j];
        acc2 += sw[l0 + j * 4 + 2] * e2[j];
        acc3 += sw[l0 + j * 4 + 3] * e3[j];
    }
    atomicAdd(&g_with_attn[col], (acc0 + acc1) + (acc2 + acc3));
}

// ---- K3: prefetch comb_W+emb; PDL-sync; finish with with_attn half ----
__global__ void __launch_bounds__(256) k_rnn_in(const int* __restrict__ x,
                                                const float* __restrict__ emb,
                                                const float* __restrict__ comb_W,
                                                const float* __restrict__ comb_b) {
    int row = blockIdx.x;        // 0..1023
    int t = threadIdx.x;         // 0..255
    const float* erow = emb + (long long)x[0] * H;
    const float* wrow = comb_W + (long long)row * 2 * H;
    int j = t * 4;
    // independent loads (inputs only)
    float4 w0 = *(const float4*)(wrow + j);
    float4 c0 = *(const float4*)(erow + j);
    float4 w1 = *(const float4*)(wrow + H + j);

    cudaGridDependencySynchronize();    // wait for K2 (g_with_attn)

    float4 c1 = *(const float4*)(g_with_attn + j);
    float acc = dot4(w0, c0) + dot4(w1, c1);
    acc = warp_sum(acc);
    __shared__ float s[8];
    if ((t & 31) == 0) s[t >> 5] = acc;
    __syncthreads();
    if (t < 8) {
        float v = s[t];
#pragma unroll
        for (int o = 4; o > 0; o >>= 1) v += __shfl_xor_sync(0xffu, v, o);
        if (t == 0) g_rnn_in[row] = fmaxf(v + comb_b[row], 0.f);
    }
}

// ---- K4: GRU input side only (gh precomputed in K2). block i: 12 warps =
//          3 gates x 4 column-quarters of W_ih; weights prefetched pre-sync ----
__global__ void __launch_bounds__(384) k_gru(const float* __restrict__ hidden,
                                             const float* __restrict__ W_ih,
                                             const float* __restrict__ b_ih,
                                             float* __restrict__ out_h) {
    int i = blockIdx.x;              // hidden index 0..1023
    int w = threadIdx.x >> 5;        // 0..11
    int lane = threadIdx.x & 31;
    int g = w >> 2;                  // gate 0..2
    int q = w & 3;                   // column quarter 0..3
    int base = q * 256;
    const float* row = W_ih + (long long)(g * H + i) * H + base;
    // weight loads are input-only: prefetch before the dependency sync
    float4 a0 = *(const float4*)(row + lane * 4);
    float4 a1 = *(const float4*)(row + 128 + lane * 4);

    cudaGridDependencySynchronize();    // wait for K3 (g_rnn_in)

    float acc = dot4(a0, *(const float4*)(g_rnn_in + base + lane * 4))
              + dot4(a1, *(const float4*)(g_rnn_in + base + 128 + lane * 4));
    acc = warp_sum(acc);
    __shared__ float s[12];
    if (lane == 0) s[w] = acc;
    __syncthreads();
    if (threadIdx.x == 0) {
        float gx_r = (s[0] + s[1]) + (s[2] + s[3])  + b_ih[0 * H + i];
        float gx_z = (s[4] + s[5]) + (s[6] + s[7])  + b_ih[1 * H + i];
        float gx_n = (s[8] + s[9]) + (s[10] + s[11]) + b_ih[2 * H + i];
        float r = 1.f / (1.f + expf(-(gx_r + g_gh[0 * H + i])));
        float z = 1.f / (1.f + expf(-(gx_z + g_gh[1 * H + i])));
        float n = tanhf(gx_n + r * g_gh[2 * H + i]);
        float h = (1.f - z) * n + z * hidden[i];
        g_hnew[i] = h;
        out_h[i] = h;
    }
}

// ---- K5: big vocab GEMV + in-loop sum-exp; PDL-sync ----
__global__ void __launch_bounds__(256, 2) k_logits(const float* __restrict__ out_W,
                                                   const float* __restrict__ out_b) {
    int lane = threadIdx.x & 31;
    int warp = (blockIdx.x * blockDim.x + threadIdx.x) >> 5;
    int nwarps = (gridDim.x * blockDim.x) >> 5;

    cudaGridDependencySynchronize();    // wait for K4 (g_hnew); CTA ramp overlapped

    float4 h[8];
#pragma unroll
    for (int k = 0; k < 8; k++)
        h[k] = *(const float4*)(g_hnew + k * 128 + lane * 4);
    float se = 0.f;
    for (int v0 = warp * 2; v0 < V - 1; v0 += nwarps * 2) {
        const float* row0 = out_W + (long long)v0 * H + lane * 4;
        const float* row1 = row0 + H;
        float4 a0[8], a1[8];
#pragma unroll
        for (int k = 0; k < 8; k++) a0[k] = __ldcs((const float4*)(row0 + k * 128));
#pragma unroll
        for (int k = 0; k < 8; k++) a1[k] = __ldcs((const float4*)(row1 + k * 128));
        float acc0 = 0.f, acc1 = 0.f;
#pragma unroll
        for (int k = 0; k < 8; k++) {
            acc0 += dot4(a0[k], h[k]);
            acc1 += dot4(a1[k], h[k]);
        }
        acc0 = warp_sum(acc0);
        acc1 = warp_sum(acc1);
        if (lane == 0) {
            float lg0 = acc0 + out_b[v0];
            float lg1 = acc1 + out_b[v0 + 1];
            g_logits[v0] = lg0;
            g_logits[v0 + 1] = lg1;
            se += expf(lg0) + expf(lg1);
        }
    }
    // tail: last row (V odd) handled by warp 0
    if (warp == 0) {
        int v = V - 1;
        const float* row = out_W + (long long)v * H + lane * 4;
        float acc = 0.f;
#pragma unroll
        for (int k = 0; k < 8; k++)
            acc += dot4(__ldcs((const float4*)(row + k * 128)), h[k]);
        acc = warp_sum(acc);
        if (lane == 0) {
            float lg = acc + out_b[v];
            g_logits[v] = lg;
            se += expf(lg);
        }
    }
    if (lane == 0) atomicAdd(&g_sumexp, se);
}

// ---- K6: single-pass writeout: logp[v] = logit[v] - log(sumexp) ----
__global__ void __launch_bounds__(256) k_logsoftmax(float* __restrict__ out) {
    cudaGridDependencySynchronize();    // wait for K5 (g_logits, g_sumexp)
    const int NV4 = V / 4;               // 12564 full float4 groups
    float lse = logf(g_sumexp);
    int idx = blockIdx.x * blockDim.x + threadIdx.x;
    int stride = gridDim.x * blockDim.x;
    for (int q = idx; q < NV4; q += stride) {
        float4 lg = *(const float4*)(g_logits + q * 4);
        lg.x -= lse; lg.y -= lse; lg.z -= lse; lg.w -= lse;
        *(float4*)(out + q * 4) = lg;
    }
    if (idx == 0) out[V - 1] = g_logits[V - 1] - lse;
}

// PDL launch helper
template <typename F, typename... Args>
static inline void pdl(dim3 g, dim3 b, F f, Args... args) {
    cudaLaunchConfig_t cfg = {};
    cfg.gridDim = g;
    cfg.blockDim = b;
    cfg.stream = 0;
    cudaLaunchAttribute at[1];
    at[0].id = cudaLaunchAttributeProgrammaticStreamSerialization;
    at[0].val.programmaticStreamSerializationAllowed = 1;
    cfg.attrs = at;
    cfg.numAttrs = 1;
    cudaLaunchKernelEx(&cfg, f, args...);
}

extern "C" void kernel_launch(void* const* d_in, const int* in_sizes, int n_in,
                              void* d_out, int out_size) {
    const int*   x       = (const int*)d_in[0];
    const float* hidden  = (const float*)d_in[1];
    const float* enc     = (const float*)d_in[2];
    const float* emb     = (const float*)d_in[3];
    const float* attn_W  = (const float*)d_in[4];
    const float* attn_b  = (const float*)d_in[5];
    const float* comb_W  = (const float*)d_in[6];
    const float* comb_b  = (const float*)d_in[7];
    const float* W_ih    = (const float*)d_in[8];
    const float* W_hh    = (const float*)d_in[9];
    const float* b_ih    = (const float*)d_in[10];
    const float* b_hh    = (const float*)d_in[11];
    const float* out_W   = (const float*)d_in[12];
    const float* out_b   = (const float*)d_in[13];
    float* out = (float*)d_out;   // layout: [logp V][h_new H][attn_w L]

    k_attn_logits<<<L + 1, 256>>>(x, hidden, emb, attn_W, attn_b);
    pdl(dim3(16 + 384), dim3(256), k_with_attn, enc, hidden, W_hh, b_hh, out + V + H);
    pdl(dim3(H), dim3(256), k_rnn_in, x, emb, comb_W, comb_b);
    pdl(dim3(H), dim3(384), k_gru, hidden, W_ih, b_ih, out + V);
    pdl(dim3(296), dim3(256), k_logits, out_W, out_b);
    pdl(dim3(256), dim3(256), k_logsoftmax, out);
}

// round 17
// speedup vs baseline: 1.0308x; 1.0308x over previous
#include <cuda_runtime.h>
#include <math.h>

#define H 1024
#define L 128
#define V 50257

// ---- scratch (device globals; no allocation allowed) ----
__device__ __align__(16) float g_attn_logits[L];
__device__ __align__(16) float g_with_attn[H];
__device__ __align__(16) float g_rnn_in[H];
__device__ __align__(16) float g_hnew[H];
__device__ __align__(16) float g_logits[V + 3];
__device__ float g_sumexp;

__device__ __forceinline__ float warp_sum(float v) {
#pragma unroll
    for (int o = 16; o > 0; o >>= 1) v += __shfl_xor_sync(0xffffffffu, v, o);
    return v;
}

__device__ __forceinline__ float dot4(float4 a, float4 b) {
    return a.x * b.x + a.y * b.y + a.z * b.z + a.w * b.w;
}

// ---- K1: attention logits (blocks 0..127) + init (block 128) ----
__global__ void __launch_bounds__(256) k_attn_logits(const int* __restrict__ x,
                              const float* __restrict__ hidden,
                              const float* __restrict__ emb,
                              const float* __restrict__ attn_W,
                              const float* __restrict__ attn_b) {
    int l = blockIdx.x;
    int t = threadIdx.x;         // 0..255
    if (l == 128) {              // init block: zero with_attn, reset scalars
        *(float4*)(g_with_attn + t * 4) = make_float4(0.f, 0.f, 0.f, 0.f);
        if (t == 0) g_sumexp = 0.f;
        return;
    }
    const float* erow = emb + (long long)x[0] * H;
    const float* wrow = attn_W + (long long)l * 2 * H;
    int j = t * 4;
    float4 w0 = *(const float4*)(wrow + j);
    float4 c0 = *(const float4*)(erow + j);
    float4 w1 = *(const float4*)(wrow + H + j);
    float4 c1 = *(const float4*)(hidden + j);
    float acc = dot4(w0, c0) + dot4(w1, c1);
    acc = warp_sum(acc);
    __shared__ float s[8];
    if ((t & 31) == 0) s[t >> 5] = acc;
    __syncthreads();
    if (t < 8) {
        float v = s[t];
#pragma unroll
        for (int o = 4; o > 0; o >>= 1) v += __shfl_xor_sync(0xffu, v, o);
        if (t == 0) g_attn_logits[l] = v + attn_b[l];
    }
}

// ---- K2: prefetch enc; PDL-sync; softmax (per block) + with_attn partials ----
__global__ void __launch_bounds__(256) k_with_attn(const float* __restrict__ enc,
                                                   float* __restrict__ out_attn) {
    __shared__ float w[L];
    __shared__ float redm[4], reds[4];
    int t = threadIdx.x;
    int col = blockIdx.x * 256 + t;
    int l0 = blockIdx.y * 32;
    // prefetch this block's enc chunk (independent of K1) into registers
    float e0[8];
#pragma unroll
    for (int j = 0; j < 8; j++) e0[j] = __ldg(enc + (l0 + j * 4) * H + col);
    float e1[8];
#pragma unroll
    for (int j = 0; j < 8; j++) e1[j] = __ldg(enc + (l0 + j * 4 + 1) * H + col);
    float e2[8];
#pragma unroll
    for (int j = 0; j < 8; j++) e2[j] = __ldg(enc + (l0 + j * 4 + 2) * H + col);
    float e3[8];
#pragma unroll
    for (int j = 0; j < 8; j++) e3[j] = __ldg(enc + (l0 + j * 4 + 3) * H + col);

    cudaGridDependencySynchronize();    // wait for K1 (attn logits + init)

    float v = 0.f;
    if (t < L) {
        v = g_attn_logits[t];
        float m = v;
#pragma unroll
        for (int o = 16; o > 0; o >>= 1) m = fmaxf(m, __shfl_xor_sync(0xffffffffu, m, o));
        if ((t & 31) == 0) redm[t >> 5] = m;
    }
    __syncthreads();
    float m4 = fmaxf(fmaxf(redm[0], redm[1]), fmaxf(redm[2], redm[3]));
    if (t < L) {
        float e = expf(v - m4);
        float ss = warp_sum(e);
        if ((t & 31) == 0) reds[t >> 5] = ss;
        w[t] = e;
    }
    __syncthreads();
    float tot = (reds[0] + reds[1]) + (reds[2] + reds[3]);
    if (t < L) {
        w[t] = w[t] / tot;
        if (blockIdx.x == 0 && blockIdx.y == 0) out_attn[t] = w[t];
    }
    __syncthreads();
    float acc0 = 0.f, acc1 = 0.f, acc2 = 0.f, acc3 = 0.f;
#pragma unroll
    for (int j = 0; j < 8; j++) {
        acc0 += w[l0 + j * 4 + 0] * e0[j];
        acc1 += w[l0 + j * 4 + 1] * e1[j];
        acc2 += w[l0 + j * 4 + 2] * e2[j];
        acc3 += w[l0 + j * 4 + 3] * e3[j];
    }
    atomicAdd(&g_with_attn[col], (acc0 + acc1) + (acc2 + acc3));
}

// ---- K3: prefetch comb_W+emb; PDL-sync; finish with with_attn half ----
__global__ void __launch_bounds__(256) k_rnn_in(const int* __restrict__ x,
                                                const float* __restrict__ emb,
                                                const float* __restrict__ comb_W,
                                                const float* __restrict__ comb_b) {
    int row = blockIdx.x;        // 0..1023
    int t = threadIdx.x;         // 0..255
    const float* erow = emb + (long long)x[0] * H;
    const float* wrow = comb_W + (long long)row * 2 * H;
    int j = t * 4;
    // independent loads (inputs only)
    float4 w0 = *(const float4*)(wrow + j);
    float4 c0 = *(const float4*)(erow + j);
    float4 w1 = *(const float4*)(wrow + H + j);

    cudaGridDependencySynchronize();    // wait for K2 (g_with_attn)

    float4 c1 = *(const float4*)(g_with_attn + j);
    float acc = dot4(w0, c0) + dot4(w1, c1);
    acc = warp_sum(acc);
    __shared__ float s[8];
    if ((t & 31) == 0) s[t >> 5] = acc;
    __syncthreads();
    if (t < 8) {
        float v = s[t];
#pragma unroll
        for (int o = 4; o > 0; o >>= 1) v += __shfl_xor_sync(0xffu, v, o);
        if (t == 0) g_rnn_in[row] = fmaxf(v + comb_b[row], 0.f);
    }
}

// ---- K4: GRU. prefetch weights (all) + hidden-side vec pre-sync;
//          only rnn_in-side vec loads wait on K3 ----
__global__ void __launch_bounds__(384) k_gru(const float* __restrict__ hidden,
                                             const float* __restrict__ W_ih,
                                             const float* __restrict__ W_hh,
                                             const float* __restrict__ b_ih,
                                             const float* __restrict__ b_hh,
                                             float* __restrict__ out_h) {
    int i = blockIdx.x;              // hidden index 0..1023
    int w = threadIdx.x >> 5;        // 0..11
    int lane = threadIdx.x & 31;
    int d = w >> 1;                  // dot index 0..5
    int half = w & 1;                // which 512-col half
    int g = (d < 3) ? d : (d - 3);
    bool hside = (d >= 3);
    const float* row = hside ? (W_hh + (long long)(g * H + i) * H)
                             : (W_ih + (long long)(g * H + i) * H);
    int base = half * 512;
    // weight loads are input-only: prefetch before the dependency sync
    float4 a[4];
#pragma unroll
    for (int k = 0; k < 4; k++)
        a[k] = *(const float4*)(row + base + k * 128 + lane * 4);
    // hidden-side vector is also input-only: prefetch it too
    float4 bv[4];
    if (hside) {
#pragma unroll
        for (int k = 0; k < 4; k++)
            bv[k] = *(const float4*)(hidden + base + k * 128 + lane * 4);
    }

    cudaGridDependencySynchronize();    // wait for K3 (g_rnn_in)

    if (!hside) {
#pragma unroll
        for (int k = 0; k < 4; k++)
            bv[k] = *(const float4*)(g_rnn_in + base + k * 128 + lane * 4);
    }
    float acc = 0.f;
#pragma unroll
    for (int k = 0; k < 4; k++) acc += dot4(a[k], bv[k]);
    acc = warp_sum(acc);
    __shared__ float s[12];
    if (lane == 0) s[w] = acc;
    __syncthreads();
    if (threadIdx.x == 0) {
        float d0 = s[0]  + s[1]  + b_ih[0 * H + i];   // ih_r
        float d1 = s[2]  + s[3]  + b_ih[1 * H + i];   // ih_z
        float d2 = s[4]  + s[5]  + b_ih[2 * H + i];   // ih_n
        float d3 = s[6]  + s[7]  + b_hh[0 * H + i];   // hh_r
        float d4 = s[8]  + s[9]  + b_hh[1 * H + i];   // hh_z
        float d5 = s[10] + s[11] + b_hh[2 * H + i];   // hh_n
        float r = 1.f / (1.f + expf(-(d0 + d3)));
        float z = 1.f / (1.f + expf(-(d1 + d4)));
        float n = tanhf(d2 + r * d5);
        float h = (1.f - z) * n + z * hidden[i];
        g_hnew[i] = h;
        out_h[i] = h;
    }
}

// ---- K5: big vocab GEMV + in-loop sum-exp; first tile prefetched pre-sync ----
__global__ void __launch_bounds__(256, 2) k_logits(const float* __restrict__ out_W,
                                                   const float* __restrict__ out_b) {
    int lane = threadIdx.x & 31;
    int warp = (blockIdx.x * blockDim.x + threadIdx.x) >> 5;
    int nwarps = (gridDim.x * blockDim.x) >> 5;

    // prefetch the first iteration's weight rows (input-only) before the sync
    int vf = warp * 2;
    const float* frow0 = out_W + (long long)vf * H + lane * 4;
    float4 a0[8], a1[8];
    bool havef = (vf < V - 1);
    if (havef) {
#pragma unroll
        for (int k = 0; k < 8; k++) a0[k] = __ldcs((const float4*)(frow0 + k * 128));
#pragma unroll
        for (int k = 0; k < 8; k++) a1[k] = __ldcs((const float4*)(frow0 + H + k * 128));
    }

    cudaGridDependencySynchronize();    // wait for K4 (g_hnew)

    float4 h[8];
#pragma unroll
    for (int k = 0; k < 8; k++)
        h[k] = *(const float4*)(g_hnew + k * 128 + lane * 4);
    float se = 0.f;
    // first iteration uses prefetched tiles
    if (havef) {
        float acc0 = 0.f, acc1 = 0.f;
#pragma unroll
        for (int k = 0; k < 8; k++) {
            acc0 += dot4(a0[k], h[k]);
            acc1 += dot4(a1[k], h[k]);
        }
        acc0 = warp_sum(acc0);
        acc1 = warp_sum(acc1);
        if (lane == 0) {
            float lg0 = acc0 + out_b[vf];
            float lg1 = acc1 + out_b[vf + 1];
            g_logits[vf] = lg0;
            g_logits[vf + 1] = lg1;
            se += expf(lg0) + expf(lg1);
        }
    }
    for (int v0 = vf + nwarps * 2; v0 < V - 1; v0 += nwarps * 2) {
        const float* row0 = out_W + (long long)v0 * H + lane * 4;
        const float* row1 = row0 + H;
#pragma unroll
        for (int k = 0; k < 8; k++) a0[k] = __ldcs((const float4*)(row0 + k * 128));
#pragma unroll
        for (int k = 0; k < 8; k++) a1[k] = __ldcs((const float4*)(row1 + k * 128));
        float acc0 = 0.f, acc1 = 0.f;
#pragma unroll
        for (int k = 0; k < 8; k++) {
            acc0 += dot4(a0[k], h[k]);
            acc1 += dot4(a1[k], h[k]);
        }
        acc0 = warp_sum(acc0);
        acc1 = warp_sum(acc1);
        if (lane == 0) {
            float lg0 = acc0 + out_b[v0];
            float lg1 = acc1 + out_b[v0 + 1];
            g_logits[v0] = lg0;
            g_logits[v0 + 1] = lg1;
            se += expf(lg0) + expf(lg1);
        }
    }
    // tail: last row (V odd) handled by warp 0
    if (warp == 0) {
        int v = V - 1;
        const float* row = out_W + (long long)v * H + lane * 4;
        float acc = 0.f;
#pragma unroll
        for (int k = 0; k < 8; k++)
            acc += dot4(__ldcs((const float4*)(row + k * 128)), h[k]);
        acc = warp_sum(acc);
        if (lane == 0) {
            float lg = acc + out_b[v];
            g_logits[v] = lg;
            se += expf(lg);
        }
    }
    if (lane == 0) atomicAdd(&g_sumexp, se);
}

// ---- K6: single-pass writeout: logp[v] = logit[v] - log(sumexp) ----
__global__ void __launch_bounds__(256) k_logsoftmax(float* __restrict__ out) {
    cudaGridDependencySynchronize();    // wait for K5 (g_logits, g_sumexp)
    const int NV4 = V / 4;               // 12564 full float4 groups
    float lse = logf(g_sumexp);
    int idx = blockIdx.x * blockDim.x + threadIdx.x;
    int stride = gridDim.x * blockDim.x;
    for (int q = idx; q < NV4; q += stride) {
        float4 lg = *(const float4*)(g_logits + q * 4);
        lg.x -= lse; lg.y -= lse; lg.z -= lse; lg.w -= lse;
        *(float4*)(out + q * 4) = lg;
    }
    if (idx == 0) out[V - 1] = g_logits[V - 1] - lse;
}

// PDL launch helper
template <typename F, typename... Args>
static inline void pdl(dim3 g, dim3 b, F f, Args... args) {
    cudaLaunchConfig_t cfg = {};
    cfg.gridDim = g;
    cfg.blockDim = b;
    cfg.stream = 0;
    cudaLaunchAttribute at[1];
    at[0].id = cudaLaunchAttributeProgrammaticStreamSerialization;
    at[0].val.programmaticStreamSerializationAllowed = 1;
    cfg.attrs = at;
    cfg.numAttrs = 1;
    cudaLaunchKernelEx(&cfg, f, args...);
}

extern "C" void kernel_launch(void* const* d_in, const int* in_sizes, int n_in,
                              void* d_out, int out_size) {
    const int*   x       = (const int*)d_in[0];
    const float* hidden  = (const float*)d_in[1];
    const float* enc     = (const float*)d_in[2];
    const float* emb     = (const float*)d_in[3];
    const float* attn_W  = (const float*)d_in[4];
    const float* attn_b  = (const float*)d_in[5];
    const float* comb_W  = (const float*)d_in[6];
    const float* comb_b  = (const float*)d_in[7];
    const float* W_ih    = (const float*)d_in[8];
    const float* W_hh    = (const float*)d_in[9];
    const float* b_ih    = (const float*)d_in[10];
    const float* b_hh    = (const float*)d_in[11];
    const float* out_W   = (const float*)d_in[12];
    const float* out_b   = (const float*)d_in[13];
    float* out = (float*)d_out;   // layout: [logp V][h_new H][attn_w L]

    k_attn_logits<<<L + 1, 256>>>(x, hidden, emb, attn_W, attn_b);
    pdl(dim3(H / 256, 4), dim3(256), k_with_attn, enc, out + V + H);
    pdl(dim3(H), dim3(256), k_rnn_in, x, emb, comb_W, comb_b);
    pdl(dim3(H), dim3(384), k_gru, hidden, W_ih, W_hh, b_ih, b_hh, out + V);
    pdl(dim3(296), dim3(256), k_logits, out_W, out_b);
    pdl(dim3(256), dim3(256), k_logsoftmax, out);
}